// round 16
// baseline (speedup 1.0000x reference)
#include <cuda_runtime.h>
#include <math.h>

// Fixed problem shape
#define BB 8
#define NN 32768
#define CC 4
#define MM 11
#define HALO 10

#define THREADS 512
#define TILE 256                 // outputs(n) per block
#define NTILES (NN / TILE)       // 128
#define VROW 400                 // float4 row stride; sk2(max e=265)=397
#define AROW 400                 // float2 row stride; reused as output bounce (needs >=1056)

typedef unsigned long long u64;
struct uu2 { u64 x, y; };

__device__ __forceinline__ void unpk(u64 v, float& x, float& y) {
    asm("mov.b64 {%0, %1}, %2;" : "=f"(x), "=f"(y) : "l"(v));
}
__device__ __forceinline__ u64 ffma2(u64 a, u64 b, u64 c) {
    u64 d; asm("fma.rn.f32x2 %0, %1, %2, %3;" : "=l"(d) : "l"(a), "l"(b), "l"(c)); return d;
}
__device__ __forceinline__ u64 fmul2(u64 a, u64 b) {
    u64 d; asm("mul.rn.f32x2 %0, %1, %2;" : "=l"(d) : "l"(a), "l"(b)); return d;
}
__device__ __forceinline__ float sqrt_ap(float q) {
    float r; asm("sqrt.approx.f32 %0, %1;" : "=f"(r) : "f"(q)); return r;
}
__device__ __forceinline__ int sk2(int e) { return e + (e >> 1); }   // stride-3 slots per entry-pair

// out[b,c,n] = sum_{j=0..10} z[n-10+j] * P_{c,j}(|z|),  P = w0+w1 a+w2 a^2+w3 a^3+w4 a^4
// sample s <-> n = n0-10+s; entry e holds samples (e, e+1).
// Thread (c, L) -> outputs (nl0, nl0+1), nl0 = 2L; tap j uses entry e = nl0 + j.

__global__ __launch_bounds__(THREADS, 4)
void gmp_fir_kernel(const float* __restrict__ x,
                    const float* __restrict__ W,
                    float* __restrict__ out)
{
    __shared__ float4 s_v[CC * VROW];      // (re_e, re_{e+1}, im_e, im_{e+1})
    __shared__ float2 s_a[CC * AROW];      // (a_e, a_{e+1}); later reused as output bounce
    __shared__ __align__(16) float2 s_W2[CC * MM * 6];   // duplicated (w,w) pairs

    const int tile = blockIdx.x % NTILES;
    const int b    = blockIdx.x / NTILES;
    const int n0   = tile * TILE;

    // Weights: W[c, d*11+j] -> s_W2[(c*11+j)*6 + d] = (w, w)
    if (threadIdx.x < CC * 5 * MM) {
        const int i = threadIdx.x;
        const int c = i / 55, r = i % 55, d = r / MM, j = r % MM;
        const float w = W[i];
        s_W2[(c * MM + j) * 6 + d] = make_float2(w, w);
    }

    // Stage 2 entries per task from 3 sample loads.
    // Task (t, cp): entries 2t, 2t+1 of channel pair cp; samples 2t, 2t+1, 2t+2.
    const float4* x4 = (const float4*)x + (size_t)b * NN * 2;
    for (int i = threadIdx.x; i < 266; i += THREADS) {
        const int t = i >> 1, cp = i & 1;
        const int e0 = 2 * t;
        const int n  = n0 - HALO + e0;
        float4 v0 = make_float4(0.f, 0.f, 0.f, 0.f);
        float4 v1 = make_float4(0.f, 0.f, 0.f, 0.f);
        float4 v2 = make_float4(0.f, 0.f, 0.f, 0.f);
        if (n >= 0)     v0 = x4[(size_t)n * 2 + cp];
        if (n + 1 >= 0) v1 = x4[(size_t)(n + 1) * 2 + cp];
        const bool has2 = (t <= 131);                  // entry e0+1 <= 264
        if (has2 && n + 2 >= 0) v2 = x4[(size_t)(n + 2) * 2 + cp];

        const float a0x = sqrt_ap(v0.x * v0.x + v0.y * v0.y);
        const float a0z = sqrt_ap(v0.z * v0.z + v0.w * v0.w);
        const float a1x = sqrt_ap(v1.x * v1.x + v1.y * v1.y);
        const float a1z = sqrt_ap(v1.z * v1.z + v1.w * v1.w);
        const int c0 = 2 * cp, c1 = c0 + 1;
        const int s0 = sk2(e0);
        s_v[c0 * VROW + s0] = make_float4(v0.x, v1.x, v0.y, v1.y);
        s_v[c1 * VROW + s0] = make_float4(v0.z, v1.z, v0.w, v1.w);
        s_a[c0 * AROW + s0] = make_float2(a0x, a1x);
        s_a[c1 * AROW + s0] = make_float2(a0z, a1z);
        if (has2) {
            const float a2x = sqrt_ap(v2.x * v2.x + v2.y * v2.y);
            const float a2z = sqrt_ap(v2.z * v2.z + v2.w * v2.w);
            const int s1 = sk2(e0 + 1);
            s_v[c0 * VROW + s1] = make_float4(v1.x, v2.x, v1.y, v2.y);
            s_v[c1 * VROW + s1] = make_float4(v1.z, v2.z, v1.w, v2.w);
            s_a[c0 * AROW + s1] = make_float2(a1x, a2x);
            s_a[c1 * AROW + s1] = make_float2(a1z, a2z);
        }
    }
    __syncthreads();

    // warp -> channel (4 warps per channel); L = 0..127, outputs nl0 = 2L, 2L+1.
    const int wid  = threadIdx.x >> 5;
    const int lane = threadIdx.x & 31;
    const int c    = wid & 3;
    const int L    = ((wid >> 2) << 5) + lane;
    const int nl0  = 2 * L;
    // sk2(2L + j) = 3L + j + (j>>1): per-thread base 3L, compile-time offset per j.
    const float4* vbase = s_v + c * VROW + 3 * L;
    const float2* abase = s_a + c * AROW + 3 * L;
    const float2* wrow  = s_W2 + c * (MM * 6);

    u64 accR = 0ull, accI = 0ull;

    #pragma unroll
    for (int j = 0; j < MM; ++j) {
        const float4 V  = vbase[j + (j >> 1)];          // LDS.128, stride-3 slots: conflict-free
        const u64    aa = *(const u64*)&abase[j + (j >> 1)];
        const uu2 wAB = *(const uu2*)&wrow[j * 6 + 0];  // (W0, W1)
        const uu2 wCD = *(const uu2*)&wrow[j * 6 + 2];  // (W2, W3)
        const u64 W4  = *(const u64*)&wrow[j * 6 + 4];

        const u64 a2 = fmul2(aa, aa);
        u64 t = ffma2(aa, wAB.y, wAB.x);
        u64 q = ffma2(aa, wCD.y, wCD.x);
        q = ffma2(a2, W4, q);
        const u64 P = ffma2(a2, q, t);                  // (p at sample e, p at e+1)
        accR = ffma2(*(const u64*)&V.x, P, accR);
        accI = ffma2(*(const u64*)&V.z, P, accI);
    }

    // Bounce through smem (reuse s_a) for coalesced global stores.
    __syncthreads();
    {
        float r0, r1, i0, i1;
        unpk(accR, r0, r1); unpk(accI, i0, i1);
        int e;
        e = (nl0 + 0) * CC + c; s_a[e + (e >> 5)] = make_float2(r0, i0);
        e = (nl0 + 1) * CC + c; s_a[e + (e >> 5)] = make_float2(r1, i1);
    }
    __syncthreads();

    float2* o2 = (float2*)out + ((size_t)b * NN + n0) * CC;
    #pragma unroll
    for (int t = 0; t < (TILE * CC) / THREADS; ++t) {
        const int i = threadIdx.x + t * THREADS;
        o2[i] = s_a[i + (i >> 5)];
    }
}

extern "C" void kernel_launch(void* const* d_in, const int* in_sizes, int n_in,
                              void* d_out, int out_size)
{
    const float* x = (const float*)d_in[0];   // [B,N,C,2] fp32
    const float* W = (const float*)d_in[1];   // [C, 55]   fp32
    float* out = (float*)d_out;               // [B,N,C,2] fp32
    (void)in_sizes; (void)n_in; (void)out_size;

    gmp_fir_kernel<<<BB * NTILES, THREADS>>>(x, W, out);
}